// round 2
// baseline (speedup 1.0000x reference)
#include <cuda_runtime.h>
#include <cuda_bf16.h>

// ---------------------------------------------------------------------------
// SwinMambaBlock: LN1 -> xB=ln@Bm -> scan h_t = xB_t + h_{t-1}@A -> xr=h@Cm
//                 -> LN2 -> GELU(ln2@W1+b1)@W2+b2 + xr
// All GEMMs in TF32 mma.sync with fp32 accumulate (rel err ~3e-4).
// Window permutation handled arithmetically inside the recurrence epilogue.
// ---------------------------------------------------------------------------

#define MTOK 50176          // 16*56*56 tokens
#define DIMC 384
#define HID  1536
#define NWIN 1024           // 16 * 8 * 8 windows
#define TLEN 49

// scratch (allocation-free rule: __device__ globals)
__device__ float g_ln [(size_t)MTOK * DIMC];
__device__ float g_xB [(size_t)MTOK * DIMC];
__device__ float g_h  [(size_t)MTOK * DIMC];
__device__ float g_hid[(size_t)MTOK * HID ];
__device__ float g_H  [2 * NWIN * DIMC];     // recurrence ping-pong state

// ---------------------------------------------------------------------------
__device__ __forceinline__ unsigned f2tf32(float x) {
    unsigned r;
    asm("cvt.rna.tf32.f32 %0, %1;" : "=r"(r) : "f"(x));
    return r;
}

__device__ __forceinline__ void mma_tf32(float* d, const unsigned* a, const unsigned* b) {
    asm volatile(
        "mma.sync.aligned.m16n8k8.row.col.f32.tf32.tf32.f32 "
        "{%0,%1,%2,%3}, {%4,%5,%6,%7}, {%8,%9}, {%0,%1,%2,%3};\n"
        : "+f"(d[0]), "+f"(d[1]), "+f"(d[2]), "+f"(d[3])
        : "r"(a[0]), "r"(a[1]), "r"(a[2]), "r"(a[3]),
          "r"(b[0]), "r"(b[1]));
}

__device__ __forceinline__ float gelu_exact(float v) {
    return 0.5f * v * (1.0f + erff(v * 0.70710678118654752f));
}

// token row for (window w, step t): b=w>>6, wh=(w>>3)&7, ww=w&7, i=t/7, j=t%7
__device__ __forceinline__ int tokrow(int w, int t) {
    int b  = w >> 6;
    int wh = (w >> 3) & 7;
    int ww = w & 7;
    int i  = t / 7;
    int j  = t - i * 7;
    return (b * 56 + wh * 7 + i) * 56 + ww * 7 + j;
}

// ---------------------------------------------------------------------------
// LayerNorm: one warp per token (row of 384 fp32)
// ---------------------------------------------------------------------------
__global__ void __launch_bounds__(256) ln_kernel(
    const float* __restrict__ in, const float* __restrict__ gamma,
    const float* __restrict__ beta, float* __restrict__ out)
{
    const int token = blockIdx.x * 8 + (threadIdx.x >> 5);
    const int lane  = threadIdx.x & 31;
    const float* row = in + (size_t)token * DIMC;

    float4 v[3];
    float s = 0.f, s2 = 0.f;
#pragma unroll
    for (int i = 0; i < 3; i++) {
        v[i] = *reinterpret_cast<const float4*>(&row[(lane + 32 * i) * 4]);
        s  += v[i].x + v[i].y + v[i].z + v[i].w;
        s2 += v[i].x * v[i].x + v[i].y * v[i].y + v[i].z * v[i].z + v[i].w * v[i].w;
    }
#pragma unroll
    for (int o = 16; o; o >>= 1) {
        s  += __shfl_xor_sync(0xffffffffu, s,  o);
        s2 += __shfl_xor_sync(0xffffffffu, s2, o);
    }
    const float mu = s * (1.f / DIMC);
    const float rs = rsqrtf(s2 * (1.f / DIMC) - mu * mu + 1e-5f);

    float* orow = out + (size_t)token * DIMC;
#pragma unroll
    for (int i = 0; i < 3; i++) {
        int c = (lane + 32 * i) * 4;
        float4 g = *reinterpret_cast<const float4*>(&gamma[c]);
        float4 b = *reinterpret_cast<const float4*>(&beta[c]);
        float4 o;
        o.x = (v[i].x - mu) * rs * g.x + b.x;
        o.y = (v[i].y - mu) * rs * g.y + b.y;
        o.z = (v[i].z - mu) * rs * g.z + b.z;
        o.w = (v[i].w - mu) * rs * g.w + b.w;
        *reinterpret_cast<float4*>(&orow[c]) = o;
    }
}

__global__ void zero_kernel(float* p, int n) {
    int i = blockIdx.x * blockDim.x + threadIdx.x;
    if (i < n) p[i] = 0.f;
}

// ---------------------------------------------------------------------------
// TF32 GEMM: C[M,N] = A[M,K] @ B[K,N] (+ epilogue per MODE)
// MODE 0: plain        MODE 1: +bias, GELU       MODE 2: +bias +resid
// MODE 3: recurrence step: acc += xB[tok(w,t),:]; store to H_next and h_tok
// All dims assumed divisible by tile sizes (true for this problem).
// ---------------------------------------------------------------------------
template<int BM, int BN, int BK, int WARPS_M, int WARPS_N, int MODE>
__global__ void __launch_bounds__(WARPS_M * WARPS_N * 32)
gemm_tf32_kernel(const float* __restrict__ Ag,
                 const float* __restrict__ Bg,
                 float* __restrict__ Cg,
                 const float* __restrict__ bias,
                 const float* __restrict__ resid,
                 int M, int N, int K,
                 int t_step,
                 const float* __restrict__ xB_tok,
                 float* __restrict__ h_tok)
{
    constexpr int THREADS = WARPS_M * WARPS_N * 32;
    constexpr int WM = BM / WARPS_M;
    constexpr int WN = BN / WARPS_N;
    constexpr int MI = WM / 16;
    constexpr int NI = WN / 8;
    constexpr int SA = BK + 4;   // stride = 4*odd -> conflict-free A frag loads
    constexpr int SB = BN + 8;   // stride == 8 (mod 32) -> conflict-free B frag loads

    __shared__ unsigned As[BM][SA];
    __shared__ unsigned Bs[BK][SB];

    const int m0 = blockIdx.x * BM;
    const int n0 = blockIdx.y * BN;
    const int tid  = threadIdx.x;
    const int warp = tid >> 5;
    const int lane = tid & 31;
    const int wm = (warp / WARPS_N) * WM;
    const int wn = (warp % WARPS_N) * WN;

    float acc[MI][NI][4] = {};

    for (int k0 = 0; k0 < K; k0 += BK) {
        // load A tile (BM x BK), convert to tf32
        constexpr int A_F4 = BM * BK / 4;
#pragma unroll
        for (int i = tid; i < A_F4; i += THREADS) {
            int r  = i / (BK / 4);
            int c4 = i % (BK / 4);
            float4 v = *reinterpret_cast<const float4*>(
                &Ag[(size_t)(m0 + r) * K + k0 + c4 * 4]);
            int c = c4 * 4;
            As[r][c + 0] = f2tf32(v.x);
            As[r][c + 1] = f2tf32(v.y);
            As[r][c + 2] = f2tf32(v.z);
            As[r][c + 3] = f2tf32(v.w);
        }
        // load B tile (BK x BN)
        constexpr int B_F4 = BK * BN / 4;
#pragma unroll
        for (int i = tid; i < B_F4; i += THREADS) {
            int r  = i / (BN / 4);
            int c4 = i % (BN / 4);
            float4 v = *reinterpret_cast<const float4*>(
                &Bg[(size_t)(k0 + r) * N + n0 + c4 * 4]);
            int c = c4 * 4;
            Bs[r][c + 0] = f2tf32(v.x);
            Bs[r][c + 1] = f2tf32(v.y);
            Bs[r][c + 2] = f2tf32(v.z);
            Bs[r][c + 3] = f2tf32(v.w);
        }
        __syncthreads();

#pragma unroll
        for (int kk = 0; kk < BK; kk += 8) {
            unsigned afr[MI][4];
            unsigned bfr[NI][2];
#pragma unroll
            for (int mi = 0; mi < MI; mi++) {
                int r = wm + mi * 16 + (lane >> 2);
                int c = kk + (lane & 3);
                afr[mi][0] = As[r][c];
                afr[mi][1] = As[r + 8][c];
                afr[mi][2] = As[r][c + 4];
                afr[mi][3] = As[r + 8][c + 4];
            }
#pragma unroll
            for (int ni = 0; ni < NI; ni++) {
                int kb = kk + (lane & 3);
                int nb = wn + ni * 8 + (lane >> 2);
                bfr[ni][0] = Bs[kb][nb];
                bfr[ni][1] = Bs[kb + 4][nb];
            }
#pragma unroll
            for (int mi = 0; mi < MI; mi++)
#pragma unroll
                for (int ni = 0; ni < NI; ni++)
                    mma_tf32(acc[mi][ni], afr[mi], bfr[ni]);
        }
        __syncthreads();
    }

    // epilogue
#pragma unroll
    for (int mi = 0; mi < MI; mi++) {
#pragma unroll
        for (int ni = 0; ni < NI; ni++) {
            const int r0 = m0 + wm + mi * 16 + (lane >> 2);
            const int c0 = n0 + wn + ni * 8 + ((lane & 3) << 1);
            float2 top = make_float2(acc[mi][ni][0], acc[mi][ni][1]);
            float2 bot = make_float2(acc[mi][ni][2], acc[mi][ni][3]);

            if (MODE == 0) {
                *reinterpret_cast<float2*>(&Cg[(size_t)r0 * N + c0]) = top;
                *reinterpret_cast<float2*>(&Cg[(size_t)(r0 + 8) * N + c0]) = bot;
            } else if (MODE == 1) {
                float2 bv = *reinterpret_cast<const float2*>(&bias[c0]);
                top.x = gelu_exact(top.x + bv.x);
                top.y = gelu_exact(top.y + bv.y);
                bot.x = gelu_exact(bot.x + bv.x);
                bot.y = gelu_exact(bot.y + bv.y);
                *reinterpret_cast<float2*>(&Cg[(size_t)r0 * N + c0]) = top;
                *reinterpret_cast<float2*>(&Cg[(size_t)(r0 + 8) * N + c0]) = bot;
            } else if (MODE == 2) {
                float2 bv = *reinterpret_cast<const float2*>(&bias[c0]);
                float2 rt = *reinterpret_cast<const float2*>(&resid[(size_t)r0 * N + c0]);
                float2 rb = *reinterpret_cast<const float2*>(&resid[(size_t)(r0 + 8) * N + c0]);
                top.x += bv.x + rt.x;  top.y += bv.y + rt.y;
                bot.x += bv.x + rb.x;  bot.y += bv.y + rb.y;
                *reinterpret_cast<float2*>(&Cg[(size_t)r0 * N + c0]) = top;
                *reinterpret_cast<float2*>(&Cg[(size_t)(r0 + 8) * N + c0]) = bot;
            } else {  // MODE 3: recurrence
                const int tokT = tokrow(r0, t_step);
                const int tokB = tokrow(r0 + 8, t_step);
                float2 xt = *reinterpret_cast<const float2*>(&xB_tok[(size_t)tokT * N + c0]);
                float2 xb = *reinterpret_cast<const float2*>(&xB_tok[(size_t)tokB * N + c0]);
                top.x += xt.x;  top.y += xt.y;
                bot.x += xb.x;  bot.y += xb.y;
                *reinterpret_cast<float2*>(&Cg[(size_t)r0 * N + c0]) = top;
                *reinterpret_cast<float2*>(&Cg[(size_t)(r0 + 8) * N + c0]) = bot;
                *reinterpret_cast<float2*>(&h_tok[(size_t)tokT * N + c0]) = top;
                *reinterpret_cast<float2*>(&h_tok[(size_t)tokB * N + c0]) = bot;
            }
        }
    }
}

// ---------------------------------------------------------------------------
extern "C" void kernel_launch(void* const* d_in, const int* in_sizes, int n_in,
                              void* d_out, int out_size)
{
    const float* x    = (const float*)d_in[0];
    const float* Amat = (const float*)d_in[1];
    const float* Bm   = (const float*)d_in[2];
    const float* Cm   = (const float*)d_in[3];
    const float* ln1w = (const float*)d_in[4];
    const float* ln1b = (const float*)d_in[5];
    const float* ln2w = (const float*)d_in[6];
    const float* ln2b = (const float*)d_in[7];
    const float* W1   = (const float*)d_in[8];
    const float* b1   = (const float*)d_in[9];
    const float* W2   = (const float*)d_in[10];
    const float* b2   = (const float*)d_in[11];
    float* out = (float*)d_out;

    float *p_ln, *p_xB, *p_h, *p_hid, *p_H;
    cudaGetSymbolAddress((void**)&p_ln,  g_ln);
    cudaGetSymbolAddress((void**)&p_xB,  g_xB);
    cudaGetSymbolAddress((void**)&p_h,   g_h);
    cudaGetSymbolAddress((void**)&p_hid, g_hid);
    cudaGetSymbolAddress((void**)&p_H,   g_H);

    // 1) LN1 over all tokens (layout-agnostic)
    ln_kernel<<<MTOK / 8, 256>>>(x, ln1w, ln1b, p_ln);

    // 2) xB = LN1(x) @ Bm   (50176 x 384 x 384)
    gemm_tf32_kernel<128, 128, 16, 2, 4, 0><<<dim3(MTOK / 128, DIMC / 128), 256>>>(
        p_ln, Bm, p_xB, nullptr, nullptr, MTOK, DIMC, DIMC, 0, nullptr, nullptr);

    // 3) recurrence: h_t = xB_t + h_{t-1} @ A   (49 sequential steps, 1024-way parallel)
    zero_kernel<<<(NWIN * DIMC + 255) / 256, 256>>>(p_H, NWIN * DIMC);
    for (int t = 0; t < TLEN; t++) {
        const float* Hin  = p_H + (size_t)(t & 1) * NWIN * DIMC;
        float*       Hout = p_H + (size_t)((t + 1) & 1) * NWIN * DIMC;
        gemm_tf32_kernel<64, 64, 32, 2, 2, 3><<<dim3(NWIN / 64, DIMC / 64), 128>>>(
            Hin, Amat, Hout, nullptr, nullptr, NWIN, DIMC, DIMC, t, p_xB, p_h);
    }

    // 4) xr = h @ Cm  -> d_out (residual base, in native token layout)
    gemm_tf32_kernel<128, 128, 16, 2, 4, 0><<<dim3(MTOK / 128, DIMC / 128), 256>>>(
        p_h, Cm, out, nullptr, nullptr, MTOK, DIMC, DIMC, 0, nullptr, nullptr);

    // 5) LN2(xr)
    ln_kernel<<<MTOK / 8, 256>>>(out, ln2w, ln2b, p_ln);

    // 6) hid = GELU(ln2 @ W1 + b1)   (50176 x 1536 x 384)
    gemm_tf32_kernel<128, 128, 16, 2, 4, 1><<<dim3(MTOK / 128, HID / 128), 256>>>(
        p_ln, W1, p_hid, b1, nullptr, MTOK, HID, DIMC, 0, nullptr, nullptr);

    // 7) out = xr + hid @ W2 + b2    (50176 x 384 x 1536)
    gemm_tf32_kernel<128, 128, 16, 2, 4, 2><<<dim3(MTOK / 128, DIMC / 128), 256>>>(
        p_hid, W2, out, b2, out, MTOK, DIMC, HID, 0, nullptr, nullptr);
}

// round 3
// speedup vs baseline: 1.4409x; 1.4409x over previous
#include <cuda_runtime.h>

// ---------------------------------------------------------------------------
// SwinMambaBlock on sm_103a.
// R2 changes vs R1:
//  * recurrence: ONE persistent kernel (96 resident CTAs, A-tile held in SMEM,
//    spin global barrier between the 49 steps) instead of 49 launches.
//  * big GEMMs: cp.async double-buffered mainloop (BK=32, 2 stages). All GEMM
//    operands are pre-rounded to TF32 at production time so the mainloop moves
//    raw bytes (numerically identical to the old per-load cvt.rna).
// ---------------------------------------------------------------------------

#define MTOK 50176          // 16*56*56 tokens
#define DIMC 384
#define HID  1536
#define NWIN 1024           // 16 * 8 * 8 windows
#define TLEN 49
#define NCTA_REC 96         // 16 m-tiles x 6 n-tiles, all resident (<=148 SMs)

// scratch (allocation-free rule: __device__ globals)
__device__ float g_ln [(size_t)MTOK * DIMC];
__device__ float g_xB [(size_t)MTOK * DIMC];
__device__ float g_h  [(size_t)MTOK * DIMC];
__device__ float g_hid[(size_t)MTOK * HID ];
__device__ float g_H  [2 * NWIN * DIMC];     // recurrence ping-pong state
__device__ float g_wA [DIMC * DIMC];         // tf32-rounded weight copies
__device__ float g_wB [DIMC * DIMC];
__device__ float g_wC [DIMC * DIMC];
__device__ float g_wW1[DIMC * HID];
__device__ float g_wW2[HID * DIMC];
__device__ int   g_bar[TLEN];                // recurrence step barrier counters

// ---------------------------------------------------------------------------
__device__ __forceinline__ float tf32r(float x) {
    unsigned u;
    asm("cvt.rna.tf32.f32 %0, %1;" : "=r"(u) : "f"(x));
    return __uint_as_float(u);
}

__device__ __forceinline__ void mma_tf32(float* d, const unsigned* a, const unsigned* b) {
    asm volatile(
        "mma.sync.aligned.m16n8k8.row.col.f32.tf32.tf32.f32 "
        "{%0,%1,%2,%3}, {%4,%5,%6,%7}, {%8,%9}, {%0,%1,%2,%3};\n"
        : "+f"(d[0]), "+f"(d[1]), "+f"(d[2]), "+f"(d[3])
        : "r"(a[0]), "r"(a[1]), "r"(a[2]), "r"(a[3]),
          "r"(b[0]), "r"(b[1]));
}

__device__ __forceinline__ void cp_async16(void* smem, const void* gmem) {
    unsigned s = (unsigned)__cvta_generic_to_shared(smem);
    asm volatile("cp.async.cg.shared.global [%0], [%1], 16;\n" :: "r"(s), "l"(gmem));
}
__device__ __forceinline__ void cp_commit() { asm volatile("cp.async.commit_group;\n"); }
template<int N> __device__ __forceinline__ void cp_wait() {
    asm volatile("cp.async.wait_group %0;\n" :: "n"(N));
}

__device__ __forceinline__ float gelu_exact(float v) {
    return 0.5f * v * (1.0f + erff(v * 0.70710678118654752f));
}

// token row for (window w, step t)
__device__ __forceinline__ int tokrow(int w, int t) {
    int b  = w >> 6;
    int wh = (w >> 3) & 7;
    int ww = w & 7;
    int i  = t / 7;
    int j  = t - i * 7;
    return (b * 56 + wh * 7 + i) * 56 + ww * 7 + j;
}

// ---------------------------------------------------------------------------
// prep: round all weights to tf32 once; zero barrier counters
// ---------------------------------------------------------------------------
__global__ void __launch_bounds__(256) prep_kernel(
    const float* __restrict__ A, const float* __restrict__ Bm,
    const float* __restrict__ Cm, const float* __restrict__ W1,
    const float* __restrict__ W2)
{
    int i = blockIdx.x * blockDim.x + threadIdx.x;
    if (i < TLEN) g_bar[i] = 0;
    if (i < DIMC * DIMC) {
        g_wA[i] = tf32r(A[i]);
        g_wB[i] = tf32r(Bm[i]);
        g_wC[i] = tf32r(Cm[i]);
    }
    if (i < DIMC * HID) {
        g_wW1[i] = tf32r(W1[i]);
        g_wW2[i] = tf32r(W2[i]);
    }
}

// ---------------------------------------------------------------------------
// LayerNorm: one warp per token; output rounded to tf32 (it feeds a GEMM)
// ---------------------------------------------------------------------------
__global__ void __launch_bounds__(256) ln_kernel(
    const float* __restrict__ in, const float* __restrict__ gamma,
    const float* __restrict__ beta, float* __restrict__ out)
{
    const int token = blockIdx.x * 8 + (threadIdx.x >> 5);
    const int lane  = threadIdx.x & 31;
    const float* row = in + (size_t)token * DIMC;

    float4 v[3];
    float s = 0.f, s2 = 0.f;
#pragma unroll
    for (int i = 0; i < 3; i++) {
        v[i] = *reinterpret_cast<const float4*>(&row[(lane + 32 * i) * 4]);
        s  += v[i].x + v[i].y + v[i].z + v[i].w;
        s2 += v[i].x * v[i].x + v[i].y * v[i].y + v[i].z * v[i].z + v[i].w * v[i].w;
    }
#pragma unroll
    for (int o = 16; o; o >>= 1) {
        s  += __shfl_xor_sync(0xffffffffu, s,  o);
        s2 += __shfl_xor_sync(0xffffffffu, s2, o);
    }
    const float mu = s * (1.f / DIMC);
    const float rs = rsqrtf(s2 * (1.f / DIMC) - mu * mu + 1e-5f);

    float* orow = out + (size_t)token * DIMC;
#pragma unroll
    for (int i = 0; i < 3; i++) {
        int c = (lane + 32 * i) * 4;
        float4 g = *reinterpret_cast<const float4*>(&gamma[c]);
        float4 b = *reinterpret_cast<const float4*>(&beta[c]);
        float4 o;
        o.x = tf32r((v[i].x - mu) * rs * g.x + b.x);
        o.y = tf32r((v[i].y - mu) * rs * g.y + b.y);
        o.z = tf32r((v[i].z - mu) * rs * g.z + b.z);
        o.w = tf32r((v[i].w - mu) * rs * g.w + b.w);
        *reinterpret_cast<float4*>(&orow[c]) = o;
    }
}

// ---------------------------------------------------------------------------
// Pipelined TF32 GEMM: C[M,N] = A[M,K] @ B[K,N], inputs pre-rounded to tf32.
// MODE 0: plain   MODE 1: +bias, GELU, round   MODE 2: +bias +resid (final)
// ---------------------------------------------------------------------------
template<int BM, int BN, int BK, int WARPS_M, int WARPS_N, int MODE>
__global__ void __launch_bounds__(WARPS_M * WARPS_N * 32)
gemm_pipe(const float* __restrict__ Ag,
          const float* __restrict__ Bg,
          float* __restrict__ Cg,
          const float* __restrict__ bias,
          const float* __restrict__ resid,
          int M, int N, int K)
{
    constexpr int THREADS = WARPS_M * WARPS_N * 32;
    constexpr int WM = BM / WARPS_M;
    constexpr int WN = BN / WARPS_N;
    constexpr int MI = WM / 16;
    constexpr int NI = WN / 8;
    constexpr int SA = BK + 4;
    constexpr int SB = BN + 8;

    extern __shared__ float sm[];
    float* As = sm;                        // [2][BM][SA]
    float* Bs = sm + 2 * BM * SA;          // [2][BK][SB]

    const int m0 = blockIdx.x * BM;
    const int n0 = blockIdx.y * BN;
    const int tid  = threadIdx.x;
    const int warp = tid >> 5;
    const int lane = tid & 31;
    const int wm = (warp / WARPS_N) * WM;
    const int wn = (warp % WARPS_N) * WN;
    const int q = lane >> 2, s = lane & 3;

    const int NK = K / BK;

    auto prefetch = [&](int kt) {
        const int st = kt & 1;
        float* Ad = As + st * BM * SA;
        float* Bd = Bs + st * BK * SB;
        const int k0 = kt * BK;
        constexpr int AF4 = BM * BK / 4;
        for (int i = tid; i < AF4; i += THREADS) {
            int r = i / (BK / 4), c4 = (i % (BK / 4)) * 4;
            cp_async16(&Ad[r * SA + c4], &Ag[(size_t)(m0 + r) * K + k0 + c4]);
        }
        constexpr int BF4 = BK * BN / 4;
        for (int i = tid; i < BF4; i += THREADS) {
            int r = i / (BN / 4), c4 = (i % (BN / 4)) * 4;
            cp_async16(&Bd[r * SB + c4], &Bg[(size_t)(k0 + r) * N + n0 + c4]);
        }
        cp_commit();
    };

    float acc[MI][NI][4] = {};

    prefetch(0);
    for (int kt = 0; kt < NK; kt++) {
        if (kt + 1 < NK) { prefetch(kt + 1); cp_wait<1>(); }
        else             { cp_wait<0>(); }
        __syncthreads();

        const float* Ac = As + (kt & 1) * BM * SA;
        const float* Bc = Bs + (kt & 1) * BK * SB;
#pragma unroll
        for (int kk = 0; kk < BK; kk += 8) {
            unsigned afr[MI][4];
            unsigned bfr[NI][2];
#pragma unroll
            for (int mi = 0; mi < MI; mi++) {
                int r = wm + mi * 16 + q;
                int c = kk + s;
                afr[mi][0] = __float_as_uint(Ac[r * SA + c]);
                afr[mi][1] = __float_as_uint(Ac[(r + 8) * SA + c]);
                afr[mi][2] = __float_as_uint(Ac[r * SA + c + 4]);
                afr[mi][3] = __float_as_uint(Ac[(r + 8) * SA + c + 4]);
            }
#pragma unroll
            for (int ni = 0; ni < NI; ni++) {
                int kb = kk + s;
                int nb = wn + ni * 8 + q;
                bfr[ni][0] = __float_as_uint(Bc[kb * SB + nb]);
                bfr[ni][1] = __float_as_uint(Bc[(kb + 4) * SB + nb]);
            }
#pragma unroll
            for (int mi = 0; mi < MI; mi++)
#pragma unroll
                for (int ni = 0; ni < NI; ni++)
                    mma_tf32(acc[mi][ni], afr[mi], bfr[ni]);
        }
        __syncthreads();
    }

    // epilogue
#pragma unroll
    for (int mi = 0; mi < MI; mi++) {
#pragma unroll
        for (int ni = 0; ni < NI; ni++) {
            const int r0 = m0 + wm + mi * 16 + q;
            const int c0 = n0 + wn + ni * 8 + 2 * s;
            float2 top = make_float2(acc[mi][ni][0], acc[mi][ni][1]);
            float2 bot = make_float2(acc[mi][ni][2], acc[mi][ni][3]);

            if (MODE == 0) {
                *reinterpret_cast<float2*>(&Cg[(size_t)r0 * N + c0]) = top;
                *reinterpret_cast<float2*>(&Cg[(size_t)(r0 + 8) * N + c0]) = bot;
            } else if (MODE == 1) {
                float2 bv = *reinterpret_cast<const float2*>(&bias[c0]);
                top.x = tf32r(gelu_exact(top.x + bv.x));
                top.y = tf32r(gelu_exact(top.y + bv.y));
                bot.x = tf32r(gelu_exact(bot.x + bv.x));
                bot.y = tf32r(gelu_exact(bot.y + bv.y));
                *reinterpret_cast<float2*>(&Cg[(size_t)r0 * N + c0]) = top;
                *reinterpret_cast<float2*>(&Cg[(size_t)(r0 + 8) * N + c0]) = bot;
            } else {  // MODE 2: +bias +resid, final fp32 output
                float2 bv = *reinterpret_cast<const float2*>(&bias[c0]);
                float2 rt = *reinterpret_cast<const float2*>(&resid[(size_t)r0 * N + c0]);
                float2 rb = *reinterpret_cast<const float2*>(&resid[(size_t)(r0 + 8) * N + c0]);
                top.x += bv.x + rt.x;  top.y += bv.y + rt.y;
                bot.x += bv.x + rb.x;  bot.y += bv.y + rb.y;
                *reinterpret_cast<float2*>(&Cg[(size_t)r0 * N + c0]) = top;
                *reinterpret_cast<float2*>(&Cg[(size_t)(r0 + 8) * N + c0]) = bot;
            }
        }
    }
}

// ---------------------------------------------------------------------------
// Persistent recurrence: one kernel, 49 steps, 96 resident CTAs.
// CTA (mx, nx) owns output tile rows m0..m0+63 (windows), cols n0..n0+63.
// A-tile (384 x 64 slice of tf32-rounded A) stays in SMEM the whole kernel.
// Per step: stage h_{t-1}[m0..m0+63, 0..383] from L2 (cp.async.cg, L1 bypass),
// mma, epilogue adds gathered xB and scatters rounded h to state + token order.
// Spin barrier on g_bar[t] between steps.
// ---------------------------------------------------------------------------
__global__ void __launch_bounds__(128) rec_kernel(
    const float* __restrict__ Aw,      // g_wA [384][384], tf32-rounded
    const float* __restrict__ xB,      // [MTOK][384]
    float* __restrict__ h_tok,         // [MTOK][384] (token order, rounded)
    float* __restrict__ Hst)           // [2][NWIN][384] ping-pong
{
    // smem: At [384][72] (110592B) + Ht [64][388] (99328B) = 209920B
    extern __shared__ float sm[];
    float* At = sm;
    float* Ht = sm + 384 * 72;

    const int m0 = blockIdx.x * 64;
    const int n0 = blockIdx.y * 64;
    const int tid  = threadIdx.x;
    const int warp = tid >> 5;
    const int lane = tid & 31;
    const int wm = (warp >> 1) * 32;   // 2x2 warps -> WM=32, WN=32
    const int wn = (warp & 1) * 32;
    const int q = lane >> 2, s = lane & 3;

    // one-time A-tile load (columns n0..n0+63, all 384 rows)
    for (int i = tid; i < 384 * 16; i += 128) {
        int r = i >> 4, c4 = (i & 15) * 4;
        cp_async16(&At[r * 72 + c4], &Aw[(size_t)r * DIMC + n0 + c4]);
    }
    cp_commit(); cp_wait<0>();
    __syncthreads();

    for (int t = 0; t < TLEN; t++) {
        float* Hout = Hst + (size_t)(t & 1) * NWIN * DIMC;

        if (t == 0) {
            // h_0 = round(xB_0)
            for (int i = tid; i < 64 * 16; i += 128) {
                int r = i >> 4, c4 = (i & 15) * 4;
                int w = m0 + r;
                int tok = tokrow(w, 0);
                float4 v = *reinterpret_cast<const float4*>(
                    &xB[(size_t)tok * DIMC + n0 + c4]);
                v.x = tf32r(v.x); v.y = tf32r(v.y);
                v.z = tf32r(v.z); v.w = tf32r(v.w);
                *reinterpret_cast<float4*>(&Hout[(size_t)w * DIMC + n0 + c4]) = v;
                *reinterpret_cast<float4*>(&h_tok[(size_t)tok * DIMC + n0 + c4]) = v;
            }
        } else {
            const float* Hin = Hst + (size_t)((t + 1) & 1) * NWIN * DIMC;
            // stage h_{t-1} rows m0..m0+63, all 384 cols (L1-bypassing)
            for (int i = tid; i < 64 * 96; i += 128) {
                int r = i / 96, c4 = (i % 96) * 4;
                cp_async16(&Ht[r * 388 + c4], &Hin[(size_t)(m0 + r) * DIMC + c4]);
            }
            cp_commit(); cp_wait<0>();
            __syncthreads();

            float acc[2][4][4] = {};
#pragma unroll 4
            for (int kk = 0; kk < DIMC; kk += 8) {
                unsigned afr[2][4], bfr[4][2];
#pragma unroll
                for (int mi = 0; mi < 2; mi++) {
                    int r = wm + mi * 16 + q;
                    int c = kk + s;
                    afr[mi][0] = __float_as_uint(Ht[r * 388 + c]);
                    afr[mi][1] = __float_as_uint(Ht[(r + 8) * 388 + c]);
                    afr[mi][2] = __float_as_uint(Ht[r * 388 + c + 4]);
                    afr[mi][3] = __float_as_uint(Ht[(r + 8) * 388 + c + 4]);
                }
#pragma unroll
                for (int ni = 0; ni < 4; ni++) {
                    int kb = kk + s;
                    int nb = wn + ni * 8 + q;
                    bfr[ni][0] = __float_as_uint(At[kb * 72 + nb]);
                    bfr[ni][1] = __float_as_uint(At[(kb + 4) * 72 + nb]);
                }
#pragma unroll
                for (int mi = 0; mi < 2; mi++)
#pragma unroll
                    for (int ni = 0; ni < 4; ni++)
                        mma_tf32(acc[mi][ni], afr[mi], bfr[ni]);
            }

            // epilogue: + xB gather, round, scatter to state + token layout
#pragma unroll
            for (int mi = 0; mi < 2; mi++) {
                const int rT = m0 + wm + mi * 16 + q;
                const int rB = rT + 8;
                const int tokT = tokrow(rT, t);
                const int tokB = tokrow(rB, t);
#pragma unroll
                for (int ni = 0; ni < 4; ni++) {
                    const int c0 = n0 + wn + ni * 8 + 2 * s;
                    float2 xt = *reinterpret_cast<const float2*>(
                        &xB[(size_t)tokT * DIMC + c0]);
                    float2 xb = *reinterpret_cast<const float2*>(
                        &xB[(size_t)tokB * DIMC + c0]);
                    float2 top = make_float2(tf32r(acc[mi][ni][0] + xt.x),
                                             tf32r(acc[mi][ni][1] + xt.y));
                    float2 bot = make_float2(tf32r(acc[mi][ni][2] + xb.x),
                                             tf32r(acc[mi][ni][3] + xb.y));
                    *reinterpret_cast<float2*>(&Hout[(size_t)rT * DIMC + c0]) = top;
                    *reinterpret_cast<float2*>(&Hout[(size_t)rB * DIMC + c0]) = bot;
                    *reinterpret_cast<float2*>(&h_tok[(size_t)tokT * DIMC + c0]) = top;
                    *reinterpret_cast<float2*>(&h_tok[(size_t)tokB * DIMC + c0]) = bot;
                }
            }
        }

        // grid-wide step barrier (all 96 CTAs resident by construction)
        if (t < TLEN - 1) {
            __threadfence();
            __syncthreads();
            if (tid == 0) {
                atomicAdd(&g_bar[t], 1);
                while (*(volatile int*)&g_bar[t] < NCTA_REC) { }
            }
            __syncthreads();
        }
    }
}

// ---------------------------------------------------------------------------
extern "C" void kernel_launch(void* const* d_in, const int* in_sizes, int n_in,
                              void* d_out, int out_size)
{
    const float* x    = (const float*)d_in[0];
    const float* Amat = (const float*)d_in[1];
    const float* Bm   = (const float*)d_in[2];
    const float* Cm   = (const float*)d_in[3];
    const float* ln1w = (const float*)d_in[4];
    const float* ln1b = (const float*)d_in[5];
    const float* ln2w = (const float*)d_in[6];
    const float* ln2b = (const float*)d_in[7];
    const float* W1   = (const float*)d_in[8];
    const float* b1   = (const float*)d_in[9];
    const float* W2   = (const float*)d_in[10];
    const float* b2   = (const float*)d_in[11];
    float* out = (float*)d_out;

    float *p_ln, *p_xB, *p_h, *p_hid, *p_H, *p_wA, *p_wB, *p_wC, *p_w1, *p_w2;
    cudaGetSymbolAddress((void**)&p_ln,  g_ln);
    cudaGetSymbolAddress((void**)&p_xB,  g_xB);
    cudaGetSymbolAddress((void**)&p_h,   g_h);
    cudaGetSymbolAddress((void**)&p_hid, g_hid);
    cudaGetSymbolAddress((void**)&p_H,   g_H);
    cudaGetSymbolAddress((void**)&p_wA,  g_wA);
    cudaGetSymbolAddress((void**)&p_wB,  g_wB);
    cudaGetSymbolAddress((void**)&p_wC,  g_wC);
    cudaGetSymbolAddress((void**)&p_w1,  g_wW1);
    cudaGetSymbolAddress((void**)&p_w2,  g_wW2);

    constexpr int GS = (2 * 128 * 36 + 2 * 32 * 136) * 4;   // 71680 B
    constexpr int RS = (384 * 72 + 64 * 388) * 4;           // 209920 B
    cudaFuncSetAttribute(gemm_pipe<128,128,32,2,4,0>,
                         cudaFuncAttributeMaxDynamicSharedMemorySize, GS);
    cudaFuncSetAttribute(gemm_pipe<128,128,32,2,4,1>,
                         cudaFuncAttributeMaxDynamicSharedMemorySize, GS);
    cudaFuncSetAttribute(gemm_pipe<128,128,32,2,4,2>,
                         cudaFuncAttributeMaxDynamicSharedMemorySize, GS);
    cudaFuncSetAttribute(rec_kernel,
                         cudaFuncAttributeMaxDynamicSharedMemorySize, RS);

    // 0) round weights to tf32, zero step-barrier counters
    prep_kernel<<<(DIMC * HID + 255) / 256, 256>>>(Amat, Bm, Cm, W1, W2);

    // 1) LN1 (rounded output)
    ln_kernel<<<MTOK / 8, 256>>>(x, ln1w, ln1b, p_ln);

    // 2) xB = LN1(x) @ Bm
    gemm_pipe<128,128,32,2,4,0><<<dim3(MTOK/128, DIMC/128), 256, GS>>>(
        p_ln, p_wB, p_xB, nullptr, nullptr, MTOK, DIMC, DIMC);

    // 3) recurrence (single persistent kernel, 49 steps)
    rec_kernel<<<dim3(NWIN/64, DIMC/64), 128, RS>>>(p_wA, p_xB, p_h, p_H);

    // 4) xr = h @ Cm -> out
    gemm_pipe<128,128,32,2,4,0><<<dim3(MTOK/128, DIMC/128), 256, GS>>>(
        p_h, p_wC, out, nullptr, nullptr, MTOK, DIMC, DIMC);

    // 5) LN2 (rounded output)
    ln_kernel<<<MTOK / 8, 256>>>(out, ln2w, ln2b, p_ln);

    // 6) hid = round(GELU(ln2 @ W1 + b1))
    gemm_pipe<128,128,32,2,4,1><<<dim3(MTOK/128, HID/128), 256, GS>>>(
        p_ln, p_w1, p_hid, b1, nullptr, MTOK, HID, DIMC);

    // 7) out = xr + hid @ W2 + b2
    gemm_pipe<128,128,32,2,4,2><<<dim3(MTOK/128, DIMC/128), 256, GS>>>(
        p_hid, p_w2, out, b2, out, MTOK, DIMC, HID);
}

// round 4
// speedup vs baseline: 1.5151x; 1.0515x over previous
#include <cuda_runtime.h>

// ---------------------------------------------------------------------------
// SwinMambaBlock on sm_103a.  R3 changes vs R2:
//  * All mma fragment loads via ldmatrix.x4 (1 LDSM replaces 4 scalar LDS):
//      - A-frag: tf32 m16n8k8 A layout == four 8x4 32-bit blocks == one
//        ldmatrix.m8n8.x4.b16 with per-lane row addresses.
//      - B-frag: weights pre-TRANSPOSED (BsT[n][k]) in prep_kernel so one
//        ldmatrix.x4 covers two n-tiles' fragments.
//  * rec_kernel: 256 threads (8 warps), LDSM, split-K overlap of the h-state
//    staging with compute.
// Numerics identical to R2 (same tf32 rounding points) -> same rel_err.
// ---------------------------------------------------------------------------

#define MTOK 50176          // 16*56*56 tokens
#define DIMC 384
#define HID  1536
#define NWIN 1024           // 16 * 8 * 8 windows
#define TLEN 49
#define NCTA_REC 96         // 16 m-tiles x 6 n-tiles, all resident

// scratch (allocation-free rule: __device__ globals)
__device__ float g_ln  [(size_t)MTOK * DIMC];
__device__ float g_xB  [(size_t)MTOK * DIMC];
__device__ float g_h   [(size_t)MTOK * DIMC];
__device__ float g_hid [(size_t)MTOK * HID ];
__device__ float g_H   [2 * NWIN * DIMC];    // recurrence ping-pong state
__device__ float g_wAT [DIMC * DIMC];        // tf32-rounded, TRANSPOSED [n][k]
__device__ float g_wBT [DIMC * DIMC];
__device__ float g_wCT [DIMC * DIMC];
__device__ float g_wW1T[HID  * DIMC];        // [1536][384]
__device__ float g_wW2T[DIMC * HID ];        // [384][1536]
__device__ int   g_bar [TLEN];

// ---------------------------------------------------------------------------
__device__ __forceinline__ float tf32r(float x) {
    unsigned u;
    asm("cvt.rna.tf32.f32 %0, %1;" : "=r"(u) : "f"(x));
    return __uint_as_float(u);
}

__device__ __forceinline__ void mma_tf32(float* d, const unsigned* a, const unsigned* b) {
    asm volatile(
        "mma.sync.aligned.m16n8k8.row.col.f32.tf32.tf32.f32 "
        "{%0,%1,%2,%3}, {%4,%5,%6,%7}, {%8,%9}, {%0,%1,%2,%3};\n"
        : "+f"(d[0]), "+f"(d[1]), "+f"(d[2]), "+f"(d[3])
        : "r"(a[0]), "r"(a[1]), "r"(a[2]), "r"(a[3]),
          "r"(b[0]), "r"(b[1]));
}

__device__ __forceinline__ void ldsm4(unsigned* r, unsigned addr) {
    asm volatile("ldmatrix.sync.aligned.m8n8.x4.shared.b16 {%0,%1,%2,%3}, [%4];"
        : "=r"(r[0]), "=r"(r[1]), "=r"(r[2]), "=r"(r[3]) : "r"(addr));
}

__device__ __forceinline__ void cp_async16(void* smem, const void* gmem) {
    unsigned s = (unsigned)__cvta_generic_to_shared(smem);
    asm volatile("cp.async.cg.shared.global [%0], [%1], 16;\n" :: "r"(s), "l"(gmem));
}
__device__ __forceinline__ void cp_commit() { asm volatile("cp.async.commit_group;\n"); }
template<int N> __device__ __forceinline__ void cp_wait() {
    asm volatile("cp.async.wait_group %0;\n" :: "n"(N));
}

__device__ __forceinline__ float gelu_exact(float v) {
    return 0.5f * v * (1.0f + erff(v * 0.70710678118654752f));
}

__device__ __forceinline__ int tokrow(int w, int t) {
    int b  = w >> 6;
    int wh = (w >> 3) & 7;
    int ww = w & 7;
    int i  = t / 7;
    int j  = t - i * 7;
    return (b * 56 + wh * 7 + i) * 56 + ww * 7 + j;
}

// ---------------------------------------------------------------------------
// prep: round weights to tf32 AND transpose to [n][k]; zero barrier counters
// ---------------------------------------------------------------------------
__global__ void __launch_bounds__(256) prep_kernel(
    const float* __restrict__ A, const float* __restrict__ Bm,
    const float* __restrict__ Cm, const float* __restrict__ W1,
    const float* __restrict__ W2)
{
    int i = blockIdx.x * blockDim.x + threadIdx.x;
    if (i < TLEN) g_bar[i] = 0;
    if (i < DIMC * DIMC) {
        int n = i / DIMC, k = i % DIMC;
        g_wAT[i] = tf32r(A [k * DIMC + n]);
        g_wBT[i] = tf32r(Bm[k * DIMC + n]);
        g_wCT[i] = tf32r(Cm[k * DIMC + n]);
    }
    if (i < HID * DIMC) {           // W1T [1536][384]
        int n = i / DIMC, k = i % DIMC;
        g_wW1T[i] = tf32r(W1[k * HID + n]);
    }
    if (i < DIMC * HID) {           // W2T [384][1536]
        int n = i / HID, k = i % HID;
        g_wW2T[i] = tf32r(W2[k * DIMC + n]);
    }
}

// ---------------------------------------------------------------------------
// LayerNorm: one warp per token; output rounded to tf32 (feeds a GEMM)
// ---------------------------------------------------------------------------
__global__ void __launch_bounds__(256) ln_kernel(
    const float* __restrict__ in, const float* __restrict__ gamma,
    const float* __restrict__ beta, float* __restrict__ out)
{
    const int token = blockIdx.x * 8 + (threadIdx.x >> 5);
    const int lane  = threadIdx.x & 31;
    const float* row = in + (size_t)token * DIMC;

    float4 v[3];
    float s = 0.f, s2 = 0.f;
#pragma unroll
    for (int i = 0; i < 3; i++) {
        v[i] = *reinterpret_cast<const float4*>(&row[(lane + 32 * i) * 4]);
        s  += v[i].x + v[i].y + v[i].z + v[i].w;
        s2 += v[i].x * v[i].x + v[i].y * v[i].y + v[i].z * v[i].z + v[i].w * v[i].w;
    }
#pragma unroll
    for (int o = 16; o; o >>= 1) {
        s  += __shfl_xor_sync(0xffffffffu, s,  o);
        s2 += __shfl_xor_sync(0xffffffffu, s2, o);
    }
    const float mu = s * (1.f / DIMC);
    const float rs = rsqrtf(s2 * (1.f / DIMC) - mu * mu + 1e-5f);

    float* orow = out + (size_t)token * DIMC;
#pragma unroll
    for (int i = 0; i < 3; i++) {
        int c = (lane + 32 * i) * 4;
        float4 g = *reinterpret_cast<const float4*>(&gamma[c]);
        float4 b = *reinterpret_cast<const float4*>(&beta[c]);
        float4 o;
        o.x = tf32r((v[i].x - mu) * rs * g.x + b.x);
        o.y = tf32r((v[i].y - mu) * rs * g.y + b.y);
        o.z = tf32r((v[i].z - mu) * rs * g.z + b.z);
        o.w = tf32r((v[i].w - mu) * rs * g.w + b.w);
        *reinterpret_cast<float4*>(&orow[c]) = o;
    }
}

// ---------------------------------------------------------------------------
// Pipelined TF32 GEMM with LDSM frag loads.
// C[M,N] = A[M,K] @ B[K,N]; Bg is pre-TRANSPOSED [N][K]; inputs tf32-rounded.
// MODE 0: plain   MODE 1: +bias, GELU, round   MODE 2: +bias +resid (final)
// ---------------------------------------------------------------------------
template<int MODE>
__global__ void __launch_bounds__(256, 2)
gemm_pipe(const float* __restrict__ Ag,
          const float* __restrict__ BgT,
          float* __restrict__ Cg,
          const float* __restrict__ bias,
          const float* __restrict__ resid,
          int M, int N, int K)
{
    constexpr int BM = 128, BN = 128, BK = 32;
    constexpr int MI = 4, NI = 4;          // warp tile 64x32, warps 2x4
    constexpr int SA = BK + 4;             // 36 floats = 144B stride
    constexpr int SB = BK + 4;

    extern __shared__ float sm[];
    float* As = sm;                        // [2][BM][SA]
    float* Bs = sm + 2 * BM * SA;          // [2][BN][SB] (transposed tile)

    const int m0 = blockIdx.x * BM;
    const int n0 = blockIdx.y * BN;
    const int tid  = threadIdx.x;
    const int warp = tid >> 5;
    const int lane = tid & 31;
    const int wm = (warp >> 2) * 64;       // WARPS_M=2
    const int wn = (warp & 3) * 32;        // WARPS_N=4
    const int q = lane >> 2, s = lane & 3;

    // LDSM per-lane offsets
    const int a_row = lane & 15;           // + wm + mi*16
    const int a_col = (lane >> 4) << 2;    // 0 or 4
    const int b_row = (((lane >> 4) & 1) << 3) + (lane & 7);  // + wn + nio*16
    const int b_col = ((lane >> 3) & 1) << 2;                 // 0 or 4

    const int NK = K / BK;

    auto prefetch = [&](int kt) {
        const int st = kt & 1;
        float* Ad = As + st * BM * SA;
        float* Bd = Bs + st * BN * SB;
        const int k0 = kt * BK;
#pragma unroll
        for (int i = tid; i < BM * (BK / 4); i += 256) {
            int r = i >> 3, c4 = (i & 7) << 2;
            cp_async16(&Ad[r * SA + c4], &Ag[(size_t)(m0 + r) * K + k0 + c4]);
        }
#pragma unroll
        for (int i = tid; i < BN * (BK / 4); i += 256) {
            int r = i >> 3, c4 = (i & 7) << 2;
            cp_async16(&Bd[r * SB + c4], &BgT[(size_t)(n0 + r) * K + k0 + c4]);
        }
        cp_commit();
    };

    float acc[MI][NI][4] = {};

    prefetch(0);
    for (int kt = 0; kt < NK; kt++) {
        if (kt + 1 < NK) { prefetch(kt + 1); cp_wait<1>(); }
        else             { cp_wait<0>(); }
        __syncthreads();

        const unsigned AsU = (unsigned)__cvta_generic_to_shared(As + (kt & 1) * BM * SA);
        const unsigned BsU = (unsigned)__cvta_generic_to_shared(Bs + (kt & 1) * BN * SB);

#pragma unroll
        for (int kk = 0; kk < BK; kk += 8) {
            unsigned afr[MI][4];
            unsigned bfr[NI][2];
#pragma unroll
            for (int mi = 0; mi < MI; mi++)
                ldsm4(afr[mi], AsU + (((wm + mi * 16 + a_row) * SA + kk + a_col) << 2));
#pragma unroll
            for (int nio = 0; nio < NI / 2; nio++) {
                unsigned r4[4];
                ldsm4(r4, BsU + (((wn + nio * 16 + b_row) * SB + kk + b_col) << 2));
                bfr[2 * nio][0]     = r4[0];
                bfr[2 * nio][1]     = r4[1];
                bfr[2 * nio + 1][0] = r4[2];
                bfr[2 * nio + 1][1] = r4[3];
            }
#pragma unroll
            for (int mi = 0; mi < MI; mi++)
#pragma unroll
                for (int ni = 0; ni < NI; ni++)
                    mma_tf32(acc[mi][ni], afr[mi], bfr[ni]);
        }
        __syncthreads();
    }

    // epilogue
#pragma unroll
    for (int mi = 0; mi < MI; mi++) {
#pragma unroll
        for (int ni = 0; ni < NI; ni++) {
            const int r0 = m0 + wm + mi * 16 + q;
            const int c0 = n0 + wn + ni * 8 + 2 * s;
            float2 top = make_float2(acc[mi][ni][0], acc[mi][ni][1]);
            float2 bot = make_float2(acc[mi][ni][2], acc[mi][ni][3]);

            if (MODE == 0) {
                *reinterpret_cast<float2*>(&Cg[(size_t)r0 * N + c0]) = top;
                *reinterpret_cast<float2*>(&Cg[(size_t)(r0 + 8) * N + c0]) = bot;
            } else if (MODE == 1) {
                float2 bv = *reinterpret_cast<const float2*>(&bias[c0]);
                top.x = tf32r(gelu_exact(top.x + bv.x));
                top.y = tf32r(gelu_exact(top.y + bv.y));
                bot.x = tf32r(gelu_exact(bot.x + bv.x));
                bot.y = tf32r(gelu_exact(bot.y + bv.y));
                *reinterpret_cast<float2*>(&Cg[(size_t)r0 * N + c0]) = top;
                *reinterpret_cast<float2*>(&Cg[(size_t)(r0 + 8) * N + c0]) = bot;
            } else {
                float2 bv = *reinterpret_cast<const float2*>(&bias[c0]);
                float2 rt = *reinterpret_cast<const float2*>(&resid[(size_t)r0 * N + c0]);
                float2 rb = *reinterpret_cast<const float2*>(&resid[(size_t)(r0 + 8) * N + c0]);
                top.x += bv.x + rt.x;  top.y += bv.y + rt.y;
                bot.x += bv.x + rb.x;  bot.y += bv.y + rb.y;
                *reinterpret_cast<float2*>(&Cg[(size_t)r0 * N + c0]) = top;
                *reinterpret_cast<float2*>(&Cg[(size_t)(r0 + 8) * N + c0]) = bot;
            }
        }
    }
}

// ---------------------------------------------------------------------------
// Persistent recurrence: 49 steps, 96 resident CTAs, 256 threads each.
// A-tile (transposed slice AtT[64 n][384 k]) pinned in SMEM; h-state staged
// per step with split-K overlap; LDSM fragment loads.
// ---------------------------------------------------------------------------
__global__ void __launch_bounds__(256) rec_kernel(
    const float* __restrict__ AwT,     // g_wAT [384 n][384 k]
    const float* __restrict__ xB,      // [MTOK][384]
    float* __restrict__ h_tok,         // [MTOK][384]
    float* __restrict__ Hst)           // [2][NWIN][384]
{
    constexpr int SS = 388;            // 1552B stride, LDSM conflict-free
    extern __shared__ float sm[];
    float* AtT = sm;                   // [64][388]
    float* Ht  = sm + 64 * SS;         // [64][388]

    const int m0 = blockIdx.x * 64;
    const int n0 = blockIdx.y * 64;
    const int tid  = threadIdx.x;
    const int warp = tid >> 5;
    const int lane = tid & 31;
    const int wm = (warp >> 2) * 32;   // warps 2x4, warp tile 32x16
    const int wn = (warp & 3) * 16;
    const int q = lane >> 2, s = lane & 3;

    const int a_row = lane & 15;
    const int a_col = (lane >> 4) << 2;
    const int b_row = (((lane >> 4) & 1) << 3) + (lane & 7);
    const int b_col = ((lane >> 3) & 1) << 2;

    // one-time transposed A-tile load: rows n0..n0+63 of AwT, all 384 k
    for (int i = tid; i < 64 * 96; i += 256) {
        int r = i / 96, c4 = (i % 96) * 4;
        cp_async16(&AtT[r * SS + c4], &AwT[(size_t)(n0 + r) * DIMC + c4]);
    }
    cp_commit(); cp_wait<0>();
    __syncthreads();

    const unsigned AtU = (unsigned)__cvta_generic_to_shared(AtT);
    const unsigned HtU = (unsigned)__cvta_generic_to_shared(Ht);

    for (int t = 0; t < TLEN; t++) {
        float* Hout = Hst + (size_t)(t & 1) * NWIN * DIMC;

        if (t == 0) {
            for (int i = tid; i < 64 * 96; i += 256) {
                int r = i / 96, c4 = (i % 96) * 4;
                int w = m0 + r;
                int tok = tokrow(w, 0);
                float4 v = *reinterpret_cast<const float4*>(
                    &xB[(size_t)tok * DIMC + n0 + c4]);
                v.x = tf32r(v.x); v.y = tf32r(v.y);
                v.z = tf32r(v.z); v.w = tf32r(v.w);
                if (c4 >= n0 && c4 < n0 + 64) { }  // (no-op; all cols handled below)
                // NOTE: this CTA only owns cols n0..n0+63 of h; write those.
                (void)v;
            }
            // h_0 = round(xB_0) for this CTA's 64x64 block
            for (int i = tid; i < 64 * 16; i += 256) {
                int r = i >> 4, c4 = (i & 15) * 4;
                int w = m0 + r;
                int tok = tokrow(w, 0);
                float4 v = *reinterpret_cast<const float4*>(
                    &xB[(size_t)tok * DIMC + n0 + c4]);
                v.x = tf32r(v.x); v.y = tf32r(v.y);
                v.z = tf32r(v.z); v.w = tf32r(v.w);
                *reinterpret_cast<float4*>(&Hout[(size_t)w * DIMC + n0 + c4]) = v;
                *reinterpret_cast<float4*>(&h_tok[(size_t)tok * DIMC + n0 + c4]) = v;
            }
        } else {
            const float* Hin = Hst + (size_t)((t + 1) & 1) * NWIN * DIMC;
            // stage h_{t-1}: split-K halves for overlap (64 rows x 192 cols each)
            for (int i = tid; i < 64 * 48; i += 256) {
                int r = i / 48, c4 = (i % 48) * 4;
                cp_async16(&Ht[r * SS + c4], &Hin[(size_t)(m0 + r) * DIMC + c4]);
            }
            cp_commit();
            for (int i = tid; i < 64 * 48; i += 256) {
                int r = i / 48, c4 = 192 + (i % 48) * 4;
                cp_async16(&Ht[r * SS + c4], &Hin[(size_t)(m0 + r) * DIMC + c4]);
            }
            cp_commit();

            float acc[2][2][4] = {};

#pragma unroll 1
            for (int half = 0; half < 2; half++) {
                if (half == 0) { cp_wait<1>(); } else { cp_wait<0>(); }
                __syncthreads();
                const int kbeg = half * 192, kend = kbeg + 192;
#pragma unroll 4
                for (int kk = kbeg; kk < kend; kk += 8) {
                    unsigned afr[2][4], bfr[2][2];
#pragma unroll
                    for (int mi = 0; mi < 2; mi++)
                        ldsm4(afr[mi], HtU + (((wm + mi * 16 + a_row) * SS + kk + a_col) << 2));
                    {
                        unsigned r4[4];
                        ldsm4(r4, AtU + (((wn + b_row) * SS + kk + b_col) << 2));
                        bfr[0][0] = r4[0]; bfr[0][1] = r4[1];
                        bfr[1][0] = r4[2]; bfr[1][1] = r4[3];
                    }
#pragma unroll
                    for (int mi = 0; mi < 2; mi++)
#pragma unroll
                        for (int ni = 0; ni < 2; ni++)
                            mma_tf32(acc[mi][ni], afr[mi], bfr[ni]);
                }
            }

            // epilogue: + xB gather, round, scatter
#pragma unroll
            for (int mi = 0; mi < 2; mi++) {
                const int rT = m0 + wm + mi * 16 + q;
                const int rB = rT + 8;
                const int tokT = tokrow(rT, t);
                const int tokB = tokrow(rB, t);
#pragma unroll
                for (int ni = 0; ni < 2; ni++) {
                    const int c0 = n0 + wn + ni * 8 + 2 * s;
                    float2 xt = *reinterpret_cast<const float2*>(&xB[(size_t)tokT * DIMC + c0]);
                    float2 xb = *reinterpret_cast<const float2*>(&xB[(size_t)tokB * DIMC + c0]);
                    float2 top = make_float2(tf32r(acc[mi][ni][0] + xt.x),
                                             tf32r(acc[mi][ni][1] + xt.y));
                    float2 bot = make_float2(tf32r(acc[mi][ni][2] + xb.x),
                                             tf32r(acc[mi][ni][3] + xb.y));
                    *reinterpret_cast<float2*>(&Hout[(size_t)rT * DIMC + c0]) = top;
                    *reinterpret_cast<float2*>(&Hout[(size_t)rB * DIMC + c0]) = bot;
                    *reinterpret_cast<float2*>(&h_tok[(size_t)tokT * DIMC + c0]) = top;
                    *reinterpret_cast<float2*>(&h_tok[(size_t)tokB * DIMC + c0]) = bot;
                }
            }
        }

        if (t < TLEN - 1) {
            __threadfence();
            __syncthreads();
            if (tid == 0) {
                atomicAdd(&g_bar[t], 1);
                while (*(volatile int*)&g_bar[t] < NCTA_REC) { }
            }
            __syncthreads();
        }
    }
}

// ---------------------------------------------------------------------------
extern "C" void kernel_launch(void* const* d_in, const int* in_sizes, int n_in,
                              void* d_out, int out_size)
{
    const float* x    = (const float*)d_in[0];
    const float* Amat = (const float*)d_in[1];
    const float* Bm   = (const float*)d_in[2];
    const float* Cm   = (const float*)d_in[3];
    const float* ln1w = (const float*)d_in[4];
    const float* ln1b = (const float*)d_in[5];
    const float* ln2w = (const float*)d_in[6];
    const float* ln2b = (const float*)d_in[7];
    const float* W1   = (const float*)d_in[8];
    const float* b1   = (const float*)d_in[9];
    const float* W2   = (const float*)d_in[10];
    const float* b2   = (const float*)d_in[11];
    float* out = (float*)d_out;

    float *p_ln, *p_xB, *p_h, *p_hid, *p_H, *p_AT, *p_BT, *p_CT, *p_1T, *p_2T;
    cudaGetSymbolAddress((void**)&p_ln,  g_ln);
    cudaGetSymbolAddress((void**)&p_xB,  g_xB);
    cudaGetSymbolAddress((void**)&p_h,   g_h);
    cudaGetSymbolAddress((void**)&p_hid, g_hid);
    cudaGetSymbolAddress((void**)&p_H,   g_H);
    cudaGetSymbolAddress((void**)&p_AT,  g_wAT);
    cudaGetSymbolAddress((void**)&p_BT,  g_wBT);
    cudaGetSymbolAddress((void**)&p_CT,  g_wCT);
    cudaGetSymbolAddress((void**)&p_1T,  g_wW1T);
    cudaGetSymbolAddress((void**)&p_2T,  g_wW2T);

    constexpr int GS = (2 * 128 * 36 + 2 * 128 * 36) * 4;   // 73728 B
    constexpr int RS = (64 * 388 + 64 * 388) * 4;           // 198656 B
    cudaFuncSetAttribute(gemm_pipe<0>, cudaFuncAttributeMaxDynamicSharedMemorySize, GS);
    cudaFuncSetAttribute(gemm_pipe<1>, cudaFuncAttributeMaxDynamicSharedMemorySize, GS);
    cudaFuncSetAttribute(gemm_pipe<2>, cudaFuncAttributeMaxDynamicSharedMemorySize, GS);
    cudaFuncSetAttribute(rec_kernel,   cudaFuncAttributeMaxDynamicSharedMemorySize, RS);

    // 0) round + transpose weights, zero barriers
    prep_kernel<<<(HID * DIMC + 255) / 256, 256>>>(Amat, Bm, Cm, W1, W2);

    // 1) LN1
    ln_kernel<<<MTOK / 8, 256>>>(x, ln1w, ln1b, p_ln);

    // 2) xB = LN1(x) @ Bm
    gemm_pipe<0><<<dim3(MTOK/128, DIMC/128), 256, GS>>>(
        p_ln, p_BT, p_xB, nullptr, nullptr, MTOK, DIMC, DIMC);

    // 3) recurrence
    rec_kernel<<<dim3(NWIN/64, DIMC/64), 256, RS>>>(p_AT, p_xB, p_h, p_H);

    // 4) xr = h @ Cm -> out
    gemm_pipe<0><<<dim3(MTOK/128, DIMC/128), 256, GS>>>(
        p_h, p_CT, out, nullptr, nullptr, MTOK, DIMC, DIMC);

    // 5) LN2
    ln_kernel<<<MTOK / 8, 256>>>(out, ln2w, ln2b, p_ln);

    // 6) hid = round(GELU(ln2 @ W1 + b1))
    gemm_pipe<1><<<dim3(MTOK/128, HID/128), 256, GS>>>(
        p_ln, p_1T, p_hid, b1, nullptr, MTOK, HID, DIMC);

    // 7) out = xr + hid @ W2 + b2
    gemm_pipe<2><<<dim3(MTOK/128, DIMC/128), 256, GS>>>(
        p_hid, p_2T, out, b2, out, MTOK, DIMC, HID);
}

// round 7
// speedup vs baseline: 2.1971x; 1.4501x over previous
#include <cuda_runtime.h>
#include <cuda_fp16.h>

// ---------------------------------------------------------------------------
// SwinMambaBlock on sm_103a.  R4 changes vs R3:
//  * All GEMMs switched tf32 m16n8k8 -> fp16 m16n8k16 (same 10-bit mantissa,
//    fp32 accumulate; 2x MACs/instr, 2x smaller operands everywhere).
//  * rec_kernel: 6-CTA clusters (one per m-group); barrier.cluster replaces
//    threadfence + global atomic spin. m-groups run decoupled.
// ---------------------------------------------------------------------------

#define MTOK 50176          // 16*56*56 tokens
#define DIMC 384
#define HID  1536
#define NWIN 1024           // 16 * 8 * 8 windows
#define TLEN 49

// scratch (allocation-free rule: __device__ globals)
__device__ __half g_ln  [(size_t)MTOK * DIMC];
__device__ float  g_xB  [(size_t)MTOK * DIMC];
__device__ __half g_h   [(size_t)MTOK * DIMC];
__device__ __half g_hid [(size_t)MTOK * HID ];
__device__ __half g_H   [2 * NWIN * DIMC];    // recurrence ping-pong (fp16)
__device__ __half g_wAT [DIMC * DIMC];        // fp16, TRANSPOSED [n][k]
__device__ __half g_wBT [DIMC * DIMC];
__device__ __half g_wCT [DIMC * DIMC];
__device__ __half g_wW1T[HID  * DIMC];        // [1536][384]
__device__ __half g_wW2T[DIMC * HID ];        // [384][1536]

// ---------------------------------------------------------------------------
__device__ __forceinline__ void mma_f16(float* d, const unsigned* a, const unsigned* b) {
    asm volatile(
        "mma.sync.aligned.m16n8k16.row.col.f32.f16.f16.f32 "
        "{%0,%1,%2,%3}, {%4,%5,%6,%7}, {%8,%9}, {%0,%1,%2,%3};\n"
        : "+f"(d[0]), "+f"(d[1]), "+f"(d[2]), "+f"(d[3])
        : "r"(a[0]), "r"(a[1]), "r"(a[2]), "r"(a[3]),
          "r"(b[0]), "r"(b[1]));
}

__device__ __forceinline__ void ldsm4(unsigned* r, unsigned addr) {
    asm volatile("ldmatrix.sync.aligned.m8n8.x4.shared.b16 {%0,%1,%2,%3}, [%4];"
        : "=r"(r[0]), "=r"(r[1]), "=r"(r[2]), "=r"(r[3]) : "r"(addr));
}

__device__ __forceinline__ void cp_async16(void* smem, const void* gmem) {
    unsigned s = (unsigned)__cvta_generic_to_shared(smem);
    asm volatile("cp.async.cg.shared.global [%0], [%1], 16;\n" :: "r"(s), "l"(gmem));
}
__device__ __forceinline__ void cp_commit() { asm volatile("cp.async.commit_group;\n"); }
template<int N> __device__ __forceinline__ void cp_wait() {
    asm volatile("cp.async.wait_group %0;\n" :: "n"(N));
}

#define CLUSTER_ARRIVE() asm volatile("barrier.cluster.arrive.aligned;" ::: "memory")
#define CLUSTER_WAIT()   asm volatile("barrier.cluster.wait.aligned;"   ::: "memory")

__device__ __forceinline__ float gelu_exact(float v) {
    return 0.5f * v * (1.0f + erff(v * 0.70710678118654752f));
}

__device__ __forceinline__ int tokrow(int w, int t) {
    int b  = w >> 6;
    int wh = (w >> 3) & 7;
    int ww = w & 7;
    int i  = t / 7;
    int j  = t - i * 7;
    return (b * 56 + wh * 7 + i) * 56 + ww * 7 + j;
}

// ---------------------------------------------------------------------------
// prep: convert weights to fp16, transposed [n][k]
// ---------------------------------------------------------------------------
__global__ void __launch_bounds__(256) prep_kernel(
    const float* __restrict__ A, const float* __restrict__ Bm,
    const float* __restrict__ Cm, const float* __restrict__ W1,
    const float* __restrict__ W2)
{
    int i = blockIdx.x * blockDim.x + threadIdx.x;
    if (i < DIMC * DIMC) {
        int n = i / DIMC, k = i % DIMC;
        g_wAT[i] = __float2half_rn(A [k * DIMC + n]);
        g_wBT[i] = __float2half_rn(Bm[k * DIMC + n]);
        g_wCT[i] = __float2half_rn(Cm[k * DIMC + n]);
    }
    if (i < HID * DIMC) {           // W1T [1536][384]
        int n = i / DIMC, k = i % DIMC;
        g_wW1T[i] = __float2half_rn(W1[k * HID + n]);
    }
    if (i < DIMC * HID) {           // W2T [384][1536]
        int n = i / HID, k = i % HID;
        g_wW2T[i] = __float2half_rn(W2[k * DIMC + n]);
    }
}

// ---------------------------------------------------------------------------
// LayerNorm: one warp per token; fp16 output (feeds GEMM)
// ---------------------------------------------------------------------------
__global__ void __launch_bounds__(256) ln_kernel(
    const float* __restrict__ in, const float* __restrict__ gamma,
    const float* __restrict__ beta, __half* __restrict__ out)
{
    const int token = blockIdx.x * 8 + (threadIdx.x >> 5);
    const int lane  = threadIdx.x & 31;
    const float* row = in + (size_t)token * DIMC;

    float4 v[3];
    float s = 0.f, s2 = 0.f;
#pragma unroll
    for (int i = 0; i < 3; i++) {
        v[i] = *reinterpret_cast<const float4*>(&row[(lane + 32 * i) * 4]);
        s  += v[i].x + v[i].y + v[i].z + v[i].w;
        s2 += v[i].x * v[i].x + v[i].y * v[i].y + v[i].z * v[i].z + v[i].w * v[i].w;
    }
#pragma unroll
    for (int o = 16; o; o >>= 1) {
        s  += __shfl_xor_sync(0xffffffffu, s,  o);
        s2 += __shfl_xor_sync(0xffffffffu, s2, o);
    }
    const float mu = s * (1.f / DIMC);
    const float rs = rsqrtf(s2 * (1.f / DIMC) - mu * mu + 1e-5f);

    __half* orow = out + (size_t)token * DIMC;
#pragma unroll
    for (int i = 0; i < 3; i++) {
        int c = (lane + 32 * i) * 4;
        float4 g = *reinterpret_cast<const float4*>(&gamma[c]);
        float4 b = *reinterpret_cast<const float4*>(&beta[c]);
        __half2 h0 = __floats2half2_rn((v[i].x - mu) * rs * g.x + b.x,
                                       (v[i].y - mu) * rs * g.y + b.y);
        __half2 h1 = __floats2half2_rn((v[i].z - mu) * rs * g.z + b.z,
                                       (v[i].w - mu) * rs * g.w + b.w);
        uint2 pk;
        pk.x = *reinterpret_cast<unsigned*>(&h0);
        pk.y = *reinterpret_cast<unsigned*>(&h1);
        *reinterpret_cast<uint2*>(&orow[c]) = pk;
    }
}

// ---------------------------------------------------------------------------
// Pipelined FP16 GEMM, LDSM frags, fp32 accumulate.
// C[M,N] = A[M,K] @ B[K,N]; BgT pre-transposed [N][K] fp16.
// MODE 0: fp32 out   MODE 1: +bias(f32), GELU, fp16 out   MODE 2: +bias+resid, fp32 out
// ---------------------------------------------------------------------------
template<int MODE>
__global__ void __launch_bounds__(256)
gemm_h(const __half* __restrict__ Ag,
       const __half* __restrict__ BgT,
       void* __restrict__ Cv,
       const float* __restrict__ bias,
       const float* __restrict__ resid,
       int M, int N, int K)
{
    constexpr int BM = 128, BN = 128, BK = 32;
    constexpr int MI = 4, NI = 4;          // warp tile 64x32, warps 2x4
    constexpr int SH = BK + 8;             // 40 halves = 80B row stride

    extern __shared__ __half smh[];
    __half* As = smh;                      // [2][BM][SH]
    __half* Bs = smh + 2 * BM * SH;        // [2][BN][SH]

    const int m0 = blockIdx.x * BM;
    const int n0 = blockIdx.y * BN;
    const int tid  = threadIdx.x;
    const int warp = tid >> 5;
    const int lane = tid & 31;
    const int wm = (warp >> 2) * 64;       // WARPS_M=2
    const int wn = (warp & 3) * 32;        // WARPS_N=4
    const int q = lane >> 2, s = lane & 3;

    // ldmatrix per-lane offsets (halves)
    const int a_row = lane & 15;
    const int a_col = (lane >> 4) << 3;                       // 0 or 8
    const int b_row = (((lane >> 4) & 1) << 3) + (lane & 7);  // n offset
    const int b_col = ((lane >> 3) & 1) << 3;                 // 0 or 8

    const int NK = K / BK;

    auto prefetch = [&](int kt) {
        const int st = kt & 1;
        __half* Ad = As + st * BM * SH;
        __half* Bd = Bs + st * BN * SH;
        const int k0 = kt * BK;
#pragma unroll
        for (int i = tid; i < BM * (BK / 8); i += 256) {
            int r = i >> 2, c8 = (i & 3) << 3;
            cp_async16(&Ad[r * SH + c8], &Ag[(size_t)(m0 + r) * K + k0 + c8]);
        }
#pragma unroll
        for (int i = tid; i < BN * (BK / 8); i += 256) {
            int r = i >> 2, c8 = (i & 3) << 3;
            cp_async16(&Bd[r * SH + c8], &BgT[(size_t)(n0 + r) * K + k0 + c8]);
        }
        cp_commit();
    };

    float acc[MI][NI][4] = {};

    prefetch(0);
    for (int kt = 0; kt < NK; kt++) {
        if (kt + 1 < NK) { prefetch(kt + 1); cp_wait<1>(); }
        else             { cp_wait<0>(); }
        __syncthreads();

        const unsigned AsU = (unsigned)__cvta_generic_to_shared(As + (kt & 1) * BM * SH);
        const unsigned BsU = (unsigned)__cvta_generic_to_shared(Bs + (kt & 1) * BN * SH);

#pragma unroll
        for (int kk = 0; kk < BK; kk += 16) {
            unsigned afr[MI][4];
            unsigned bfr[NI][2];
#pragma unroll
            for (int mi = 0; mi < MI; mi++)
                ldsm4(afr[mi], AsU + ((wm + mi * 16 + a_row) * SH + kk + a_col) * 2);
#pragma unroll
            for (int nio = 0; nio < NI / 2; nio++) {
                unsigned r4[4];
                ldsm4(r4, BsU + ((wn + nio * 16 + b_row) * SH + kk + b_col) * 2);
                bfr[2 * nio][0]     = r4[0];
                bfr[2 * nio][1]     = r4[1];
                bfr[2 * nio + 1][0] = r4[2];
                bfr[2 * nio + 1][1] = r4[3];
            }
#pragma unroll
            for (int mi = 0; mi < MI; mi++)
#pragma unroll
                for (int ni = 0; ni < NI; ni++)
                    mma_f16(acc[mi][ni], afr[mi], bfr[ni]);
        }
        __syncthreads();
    }

    // epilogue
#pragma unroll
    for (int mi = 0; mi < MI; mi++) {
#pragma unroll
        for (int ni = 0; ni < NI; ni++) {
            const int r0 = m0 + wm + mi * 16 + q;
            const int c0 = n0 + wn + ni * 8 + 2 * s;
            float2 top = make_float2(acc[mi][ni][0], acc[mi][ni][1]);
            float2 bot = make_float2(acc[mi][ni][2], acc[mi][ni][3]);

            if (MODE == 0) {
                float* Cg = (float*)Cv;
                *reinterpret_cast<float2*>(&Cg[(size_t)r0 * N + c0]) = top;
                *reinterpret_cast<float2*>(&Cg[(size_t)(r0 + 8) * N + c0]) = bot;
            } else if (MODE == 1) {
                __half* Cg = (__half*)Cv;
                float2 bv = *reinterpret_cast<const float2*>(&bias[c0]);
                __half2 ht = __floats2half2_rn(gelu_exact(top.x + bv.x),
                                               gelu_exact(top.y + bv.y));
                __half2 hb = __floats2half2_rn(gelu_exact(bot.x + bv.x),
                                               gelu_exact(bot.y + bv.y));
                *reinterpret_cast<__half2*>(&Cg[(size_t)r0 * N + c0]) = ht;
                *reinterpret_cast<__half2*>(&Cg[(size_t)(r0 + 8) * N + c0]) = hb;
            } else {
                float* Cg = (float*)Cv;
                float2 bv = *reinterpret_cast<const float2*>(&bias[c0]);
                float2 rt = *reinterpret_cast<const float2*>(&resid[(size_t)r0 * N + c0]);
                float2 rb = *reinterpret_cast<const float2*>(&resid[(size_t)(r0 + 8) * N + c0]);
                top.x += bv.x + rt.x;  top.y += bv.y + rt.y;
                bot.x += bv.x + rb.x;  bot.y += bv.y + rb.y;
                *reinterpret_cast<float2*>(&Cg[(size_t)r0 * N + c0]) = top;
                *reinterpret_cast<float2*>(&Cg[(size_t)(r0 + 8) * N + c0]) = bot;
            }
        }
    }
}

// ---------------------------------------------------------------------------
// Persistent recurrence, cluster edition.
// Grid (6 n-tiles, 16 m-tiles), cluster = the 6 n-tiles of one m-group.
// Per step dependency spans only the cluster -> barrier.cluster, no atomics,
// no gpu-scope fences. A-tile (fp16, [64 n][384 k]) pinned in SMEM.
// ---------------------------------------------------------------------------
__global__ void __launch_bounds__(256) __cluster_dims__(6, 1, 1)
rec_kernel(const __half* __restrict__ AwT,   // [384 n][384 k] fp16
           const float*  __restrict__ xB,    // [MTOK][384] fp32
           __half* __restrict__ h_tok,       // [MTOK][384] fp16
           __half* __restrict__ Hst)         // [2][NWIN][384] fp16
{
    constexpr int SHh = 392;                 // halves; 784B row stride
    extern __shared__ __half smh[];
    __half* AtT = smh;                       // [64][392]
    __half* Ht  = smh + 64 * SHh;            // [64][392]

    const int n0 = blockIdx.x * 64;
    const int m0 = blockIdx.y * 64;
    const int tid  = threadIdx.x;
    const int warp = tid >> 5;
    const int lane = tid & 31;
    const int wm = (warp >> 2) * 32;         // warps 2x4, warp tile 32x16
    const int wn = (warp & 3) * 16;
    const int q = lane >> 2, s = lane & 3;

    const int a_row = lane & 15;
    const int a_col = (lane >> 4) << 3;
    const int b_row = (((lane >> 4) & 1) << 3) + (lane & 7);
    const int b_col = ((lane >> 3) & 1) << 3;

    // one-time A-tile load: rows n0..n0+63 of AwT, all 384 k (fp16)
    for (int i = tid; i < 64 * 48; i += 256) {
        int r = i / 48, c8 = (i % 48) * 8;
        cp_async16(&AtT[r * SHh + c8], &AwT[(size_t)(n0 + r) * DIMC + c8]);
    }
    cp_commit(); cp_wait<0>();
    __syncthreads();

    const unsigned AtU = (unsigned)__cvta_generic_to_shared(AtT);
    const unsigned HtU = (unsigned)__cvta_generic_to_shared(Ht);

    for (int t = 0; t < TLEN; t++) {
        __half* Hout = Hst + (size_t)(t & 1) * NWIN * DIMC;

        if (t == 0) {
            // h_0 = fp16(xB_0) for this CTA's 64x64 block
            for (int i = tid; i < 64 * 16; i += 256) {
                int r = i >> 4, c4 = (i & 15) * 4;
                int w = m0 + r;
                int tok = tokrow(w, 0);
                float4 v = *reinterpret_cast<const float4*>(
                    &xB[(size_t)tok * DIMC + n0 + c4]);
                __half2 h0 = __floats2half2_rn(v.x, v.y);
                __half2 h1 = __floats2half2_rn(v.z, v.w);
                uint2 pk;
                pk.x = *reinterpret_cast<unsigned*>(&h0);
                pk.y = *reinterpret_cast<unsigned*>(&h1);
                *reinterpret_cast<uint2*>(&Hout[(size_t)w * DIMC + n0 + c4]) = pk;
                *reinterpret_cast<uint2*>(&h_tok[(size_t)tok * DIMC + n0 + c4]) = pk;
            }
        } else {
            float acc[2][2][4] = {};
#pragma unroll 1
            for (int half = 0; half < 2; half++) {
                if (half == 0) { cp_wait<1>(); } else { cp_wait<0>(); }
                __syncthreads();
                const int kbeg = half * 192;
#pragma unroll 4
                for (int kk = kbeg; kk < kbeg + 192; kk += 16) {
                    unsigned afr[2][4], bfr[2][2];
#pragma unroll
                    for (int mi = 0; mi < 2; mi++)
                        ldsm4(afr[mi], HtU + ((wm + mi * 16 + a_row) * SHh + kk + a_col) * 2);
                    {
                        unsigned r4[4];
                        ldsm4(r4, AtU + ((wn + b_row) * SHh + kk + b_col) * 2);
                        bfr[0][0] = r4[0]; bfr[0][1] = r4[1];
                        bfr[1][0] = r4[2]; bfr[1][1] = r4[3];
                    }
#pragma unroll
                    for (int mi = 0; mi < 2; mi++)
#pragma unroll
                        for (int ni = 0; ni < 2; ni++)
                            mma_f16(acc[mi][ni], afr[mi], bfr[ni]);
                }
            }

            // epilogue: + xB (fp32), round fp16, scatter to state + token order
#pragma unroll
            for (int mi = 0; mi < 2; mi++) {
                const int rT = m0 + wm + mi * 16 + q;
                const int rB = rT + 8;
                const int tokT = tokrow(rT, t);
                const int tokB = tokrow(rB, t);
#pragma unroll
                for (int ni = 0; ni < 2; ni++) {
                    const int c0 = n0 + wn + ni * 8 + 2 * s;
                    float2 xt = *reinterpret_cast<const float2*>(&xB[(size_t)tokT * DIMC + c0]);
                    float2 xb = *reinterpret_cast<const float2*>(&xB[(size_t)tokB * DIMC + c0]);
                    __half2 ht = __floats2half2_rn(acc[mi][ni][0] + xt.x,
                                                   acc[mi][ni][1] + xt.y);
                    __half2 hb = __floats2half2_rn(acc[mi][ni][2] + xb.x,
                                                   acc[mi][ni][3] + xb.y);
                    *reinterpret_cast<__half2*>(&Hout[(size_t)rT * DIMC + c0]) = ht;
                    *reinterpret_cast<__half2*>(&Hout[(size_t)rB * DIMC + c0]) = hb;
                    *reinterpret_cast<__half2*>(&h_tok[(size_t)tokT * DIMC + c0]) = ht;
                    *reinterpret_cast<__half2*>(&h_tok[(size_t)tokB * DIMC + c0]) = hb;
                }
            }
        }

        // cluster barrier: Hout writes (release) -> peers' staging (acquire)
        CLUSTER_ARRIVE();
        if (t < TLEN - 1) {
            CLUSTER_WAIT();
            // stage h_t rows m0..m0+63, all 384 cols, split-K for overlap
            const __half* Hin = Hst + (size_t)(t & 1) * NWIN * DIMC;
            for (int i = tid; i < 64 * 24; i += 256) {
                int r = i / 24, c8 = (i % 24) * 8;
                cp_async16(&Ht[r * SHh + c8], &Hin[(size_t)(m0 + r) * DIMC + c8]);
            }
            cp_commit();
            for (int i = tid; i < 64 * 24; i += 256) {
                int r = i / 24, c8 = 192 + (i % 24) * 8;
                cp_async16(&Ht[r * SHh + c8], &Hin[(size_t)(m0 + r) * DIMC + c8]);
            }
            cp_commit();
        } else {
            CLUSTER_WAIT();
        }
    }
}

// ---------------------------------------------------------------------------
extern "C" void kernel_launch(void* const* d_in, const int* in_sizes, int n_in,
                              void* d_out, int out_size)
{
    const float* x    = (const float*)d_in[0];
    const float* Amat = (const float*)d_in[1];
    const float* Bm   = (const float*)d_in[2];
    const float* Cm   = (const float*)d_in[3];
    const float* ln1w = (const float*)d_in[4];
    const float* ln1b = (const float*)d_in[5];
    const float* ln2w = (const float*)d_in[6];
    const float* ln2b = (const float*)d_in[7];
    const float* W1   = (const float*)d_in[8];
    const float* b1   = (const float*)d_in[9];
    const float* W2   = (const float*)d_in[10];
    const float* b2   = (const float*)d_in[11];
    float* out = (float*)d_out;

    __half *p_ln, *p_h, *p_hid, *p_H, *p_AT, *p_BT, *p_CT, *p_1T, *p_2T;
    float *p_xB;
    cudaGetSymbolAddress((void**)&p_ln,  g_ln);
    cudaGetSymbolAddress((void**)&p_xB,  g_xB);
    cudaGetSymbolAddress((void**)&p_h,   g_h);
    cudaGetSymbolAddress((void**)&p_hid, g_hid);
    cudaGetSymbolAddress((void**)&p_H,   g_H);
    cudaGetSymbolAddress((void**)&p_AT,  g_wAT);
    cudaGetSymbolAddress((void**)&p_BT,  g_wBT);
    cudaGetSymbolAddress((void**)&p_CT,  g_wCT);
    cudaGetSymbolAddress((void**)&p_1T,  g_wW1T);
    cudaGetSymbolAddress((void**)&p_2T,  g_wW2T);

    constexpr int GS = (2 * 128 * 40 + 2 * 128 * 40) * 2;   // 40960 B
    constexpr int RS = (64 * 392 + 64 * 392) * 2;           // 100352 B
    cudaFuncSetAttribute(gemm_h<0>, cudaFuncAttributeMaxDynamicSharedMemorySize, GS);
    cudaFuncSetAttribute(gemm_h<1>, cudaFuncAttributeMaxDynamicSharedMemorySize, GS);
    cudaFuncSetAttribute(gemm_h<2>, cudaFuncAttributeMaxDynamicSharedMemorySize, GS);
    cudaFuncSetAttribute(rec_kernel, cudaFuncAttributeMaxDynamicSharedMemorySize, RS);

    // 0) weights -> fp16, transposed
    prep_kernel<<<(HID * DIMC + 255) / 256, 256>>>(Amat, Bm, Cm, W1, W2);

    // 1) LN1 -> fp16
    ln_kernel<<<MTOK / 8, 256>>>(x, ln1w, ln1b, p_ln);

    // 2) xB = LN1(x) @ Bm  (fp32 out)
    gemm_h<0><<<dim3(MTOK/128, DIMC/128), 256, GS>>>(
        p_ln, p_BT, p_xB, nullptr, nullptr, MTOK, DIMC, DIMC);

    // 3) recurrence (clustered persistent kernel)
    rec_kernel<<<dim3(6, 16), 256, RS>>>(p_AT, p_xB, p_h, p_H);

    // 4) xr = h @ Cm -> out (fp32)
    gemm_h<0><<<dim3(MTOK/128, DIMC/128), 256, GS>>>(
        p_h, p_CT, out, nullptr, nullptr, MTOK, DIMC, DIMC);

    // 5) LN2 -> fp16
    ln_kernel<<<MTOK / 8, 256>>>(out, ln2w, ln2b, p_ln);

    // 6) hid = fp16(GELU(ln2 @ W1 + b1))
    gemm_h<1><<<dim3(MTOK/128, HID/128), 256, GS>>>(
        p_ln, p_1T, p_hid, b1, nullptr, MTOK, HID, DIMC);

    // 7) out = xr + hid @ W2 + b2
    gemm_h<2><<<dim3(MTOK/128, DIMC/128), 256, GS>>>(
        p_hid, p_2T, out, b2, out, MTOK, DIMC, HID);
}